// round 14
// baseline (speedup 1.0000x reference)
#include <cuda_runtime.h>
#include <cstdint>

// ---------------------------------------------------------------------------
// MinimalQuantumLayer via Heisenberg picture, R14 = R13 math + 2 adjacent
// items per thread (two independent f32x2 pipelines):
//  - R9's ILP layout retried with its two bugs fixed: launch_bounds(256,3)
//    (R9 self-capped occupancy at 2 CTAs/SM) and R13's leaner body
//    (direct sincospi2 poly, subproduct coefs, neg2 signs, tree sums).
//  - items are memory-adjacent: 4 contiguous LDG.128, one latency exposure;
//    warp-uniform coefficient setup amortized over both pipelines.
//  - addressing: o = idx<<4, xoff = o - 8*(idx&31).
// ---------------------------------------------------------------------------

typedef unsigned long long u64x;

static __device__ __forceinline__ u64x pack2(float lo, float hi) {
    u64x r;
    asm("mov.b64 %0, {%1, %2};" : "=l"(r)
        : "r"(__float_as_uint(lo)), "r"(__float_as_uint(hi)));
    return r;
}
static __device__ __forceinline__ void unpack2(u64x v, float& lo, float& hi) {
    unsigned a, b;
    asm("mov.b64 {%0, %1}, %2;" : "=r"(a), "=r"(b) : "l"(v));
    lo = __uint_as_float(a); hi = __uint_as_float(b);
}
static __device__ __forceinline__ u64x bcast2(float f) { return pack2(f, f); }
static __device__ __forceinline__ u64x fma2(u64x a, u64x b, u64x c) {
    u64x d;
    asm("fma.rn.f32x2 %0, %1, %2, %3;" : "=l"(d) : "l"(a), "l"(b), "l"(c));
    return d;
}
static __device__ __forceinline__ u64x mul2(u64x a, u64x b) {
    u64x d;
    asm("mul.rn.f32x2 %0, %1, %2;" : "=l"(d) : "l"(a), "l"(b));
    return d;
}
static __device__ __forceinline__ u64x add2(u64x a, u64x b) {
    u64x d;
    asm("add.rn.f32x2 %0, %1, %2;" : "=l"(d) : "l"(a), "l"(b));
    return d;
}
static __device__ __forceinline__ u64x neg2(u64x a) { return a ^ 0x8000000080000000ULL; }

// sin(pi/2 u), cos(pi/2 u) for u in [0,1], Horner in u^2, pi/2 folded into
// Chebyshev-economized coefficients. err(sin) ~1e-6, err(cos) ~1e-7.
static __device__ __forceinline__ void sincospi2(u64x u, u64x& c, u64x& s) {
    const u64x A1 = bcast2(1.57079069f),  A3 = bcast2(-0.64588889f),
               A5 = bcast2(0.07942189f),  A7 = bcast2(-0.00432076f);
    const u64x B0 = bcast2(0.99999995f),  B2 = bcast2(-1.23369809f),
               B4 = bcast2(0.25364982f),  B6 = bcast2(-0.02080835f),
               B8 = bcast2(0.00085626f);
    const u64x u2 = mul2(u, u);
    u64x q = fma2(B8, u2, B6);
    q = fma2(q, u2, B4);
    q = fma2(q, u2, B2);
    c = fma2(q, u2, B0);
    u64x p = fma2(A7, u2, A5);
    p = fma2(p, u2, A3);
    p = fma2(p, u2, A1);
    s = mul2(p, u);
}

// ---------------- compile-time Pauli-string machinery ----------------------
struct PS { int x, z, ph; };

static __host__ __device__ constexpr PS conj_cnot(PS p, int c, int t) {
    const int xc = (p.x >> c) & 1, zc = (p.z >> c) & 1;
    const int xt = (p.x >> t) & 1, zt = (p.z >> t) & 1;
    const int flip = xc & zt & (xt ^ zc ^ 1);
    return PS{ p.x ^ (xc << t), p.z ^ (zt << c), (p.ph + 2 * flip) & 3 };
}
static __host__ __device__ constexpr PS conj_ring(PS p) {
    p = conj_cnot(p, 3, 0);
    p = conj_cnot(p, 2, 3);
    p = conj_cnot(p, 1, 2);
    p = conj_cnot(p, 0, 1);
    return p;
}
static __host__ __device__ constexpr PS mul_ps(PS a, PS b) {
    int ph = a.ph + b.ph;
    for (int q = 0; q < 4; ++q) {
        const int x1 = (a.x >> q) & 1, z1 = (a.z >> q) & 1;
        const int x2 = (b.x >> q) & 1, z2 = (b.z >> q) & 1;
        ph += x1 * z1 + x2 * z2 + 2 * (z1 & x2) - ((x1 ^ x2) & (z1 ^ z2));
    }
    return PS{ a.x ^ b.x, a.z ^ b.z, ((ph % 4) + 4) & 3 };
}

struct TermTab {
    int off[5];
    int tS[36];        // support mask of this term's observable
    int let[36][4];    // 0=I 1=X 2=Z 3=Y
    int sgn[36];
    int smask[36];     // bit j: factor uses sin(w2_j) (else cos)
};

static __host__ __device__ constexpr TermTab build_terms() {
    TermTab T{};
    int n = 0;
    for (int o = 0; o < 4; ++o) {
        T.off[o] = n;
        const PS Pq = conj_ring(PS{0, 1 << o, 0});   // R2' Z_o R2: pure Z-string
        const int S = Pq.z;
        for (int m = 0; m < 16; ++m) {
            if (m & ~S) continue;
            PS prod{0, 0, 0};
            for (int j = 0; j < 4; ++j) {
                if (!((S >> j) & 1)) continue;
                const PS base = ((m >> j) & 1) ? PS{1 << j, 1 << j, 0}   // Y_j
                                               : PS{0, 1 << j, 0};      // Z_j
                prod = mul_ps(prod, conj_ring(base));                   // R1-conj
            }
            T.tS[n] = S;
            for (int q = 0; q < 4; ++q) {
                const int xb = (prod.x >> q) & 1, zb = (prod.z >> q) & 1;
                T.let[n][q] = xb + 2 * zb;
            }
            T.sgn[n]   = (prod.ph == 0) ? 1 : ((prod.ph == 2) ? -1 : 0);
            T.smask[n] = m;
            ++n;
        }
    }
    T.off[4] = n;
    return T;
}

static constexpr TermTab TTC = build_terms();   // compile-time only
static_assert(TTC.off[4] == 36, "term count");

// ---------------- runtime structures (constant-index access only) -----------
struct Bloch { u64x ex[4], ey[4], ez[4]; };     // <X>, <Y>, <Z> per qubit
struct Ctx {                                    // warp-uniform weight context
    float P01[4], P23[4];                       // w2 products qubits {0,1}/{2,3}
    float c2q1, s2q1, c2q2, s2q2;               // single-qubit leftovers
    float c1[4], s1[4];                         // layer-1 weight trig
};

// coefficient of term TI: product of sin/cos(w2_j) over support (sign handled
// separately via neg2 on the packed product). Index bit j of smask selects sin.
template <int TI>
static __device__ __forceinline__ float coefv(const Ctx& C) {
    constexpr int S = TTC.tS[TI], m = TTC.smask[TI];
    constexpr bool lo2 = (S & 3) == 3;               // qubits 0 and 1
    constexpr bool lo1 = !lo2 && ((S & 2) != 0);     // qubit 1 only (o=0)
    constexpr bool hi2 = (S & 12) == 12;             // qubits 2 and 3
    constexpr bool hi1 = !hi2 && ((S & 4) != 0);     // qubit 2 only (o=2)
    if constexpr (lo2 && hi2) return C.P01[m & 3] * C.P23[(m >> 2) & 3];
    else if constexpr (lo2 && hi1)
        return C.P01[m & 3] * (((m >> 2) & 1) ? C.s2q2 : C.c2q2);
    else if constexpr (lo2) return C.P01[m & 3];
    else if constexpr (lo1 && hi2)
        return (((m >> 1) & 1) ? C.s2q1 : C.c2q1) * C.P23[(m >> 2) & 3];
    else if constexpr (hi2) return C.P23[(m >> 2) & 3];
    else return 1.0f;   // unreachable for this circuit
}

// Bloch-product of one term: X -> ex, Z -> ez, Y -> ey, I -> skip
template <int L, int Q>
static __device__ __forceinline__ u64x pick(const Bloch& B) {
    if constexpr (L == 1) return B.ex[Q];
    else if constexpr (L == 2) return B.ez[Q];
    else return B.ey[Q];
}
template <int TI>
static __device__ __forceinline__ u64x pprod(const Bloch& B) {
    constexpr int L0 = TTC.let[TI][0], L1 = TTC.let[TI][1],
                  L2 = TTC.let[TI][2], L3 = TTC.let[TI][3];
    constexpr int f = L0 ? 0 : (L1 ? 1 : (L2 ? 2 : 3));
    u64x m;
    if constexpr (f == 0)      m = pick<L0, 0>(B);
    else if constexpr (f == 1) m = pick<L1, 1>(B);
    else if constexpr (f == 2) m = pick<L2, 2>(B);
    else                       m = pick<L3, 3>(B);
    if constexpr (f < 1 && L1 != 0) m = mul2(m, pick<L1, 1>(B));
    if constexpr (f < 2 && L2 != 0) m = mul2(m, pick<L2, 2>(B));
    if constexpr (f < 3 && L3 != 0) m = mul2(m, pick<L3, 3>(B));
    return m;
}
// packed product with compile-time sign folded (neg2 = alu-pipe XOR)
template <int TI>
static __device__ __forceinline__ u64x sprod(const Bloch& B) {
    const u64x p = pprod<TI>(B);
    if constexpr (TTC.sgn[TI] < 0) return neg2(p);
    else return p;
}

// tree-split sum of terms [TI, TE): short fma chains joined by add2
template <int TI, int TE>
static __device__ __forceinline__ u64x tsum(const Bloch& B, const Ctx& C) {
    if constexpr (TE - TI == 1) {
        return mul2(sprod<TI>(B), bcast2(coefv<TI>(C)));
    } else if constexpr (TE - TI == 2) {
        return fma2(sprod<TI>(B), bcast2(coefv<TI>(C)),
                    mul2(sprod<TI + 1>(B), bcast2(coefv<TI + 1>(C))));
    } else {
        constexpr int MID = TI + (TE - TI) / 2;
        return add2(tsum<TI, MID>(B, C), tsum<MID, TE>(B, C));
    }
}

// build Bloch state for one f32x2 pipeline (two adjacent patches):
// top = pixels (row 2r, cols 4c..4c+3)'s float4, bot = row 2r+1 ditto.
static __device__ __forceinline__ Bloch make_bloch(float4 top, float4 bot,
                                                   const Ctx& C) {
    u64x ct[4], st[4];
    sincospi2(pack2(top.x, top.z), ct[0], st[0]);
    sincospi2(pack2(top.y, top.w), ct[1], st[1]);
    sincospi2(pack2(bot.x, bot.z), ct[2], st[2]);
    sincospi2(pack2(bot.y, bot.w), ct[3], st[3]);
    Bloch B;
#pragma unroll
    for (int q = 0; q < 4; ++q) {
        B.ex[q] = st[q];
        B.ey[q] = mul2(bcast2(-C.s1[q]), ct[q]);
        B.ez[q] = mul2(bcast2(C.c1[q]), ct[q]);
    }
    return B;
}

// ---------------- main kernel ---------------------------------------------
// 131072 threads = 32 (batch) * 128 (rows) * 32 (groups of 4 patches);
// pipeline A = patch cols 4g,4g+1 (f32x2 lanes), pipeline B = 4g+2,4g+3.
__global__ void __launch_bounds__(256, 3)
qmain_kernel(const float* __restrict__ x, const float* __restrict__ w8,
             float* __restrict__ out) {
    // warp-uniform weight trig (|w| <= 0.1 -> short Taylor, full angle)
    Ctx C;
    {
        float c2[4], s2[4];
        const float4 wa = __ldg(reinterpret_cast<const float4*>(w8));
        const float4 wb = __ldg(reinterpret_cast<const float4*>(w8) + 1);
        const float w1[4] = {wa.x, wa.y, wa.z, wa.w};
        const float w2[4] = {wb.x, wb.y, wb.z, wb.w};
#pragma unroll
        for (int q = 0; q < 4; ++q) {
            const float a = w1[q], a2 = a * a;
            C.c1[q] = 1.0f + a2 * (-0.5f + a2 * (1.0f / 24.0f));
            C.s1[q] = a * (1.0f + a2 * (-1.0f / 6.0f + a2 * (1.0f / 120.0f)));
            const float b = w2[q], b2 = b * b;
            c2[q] = 1.0f + b2 * (-0.5f + b2 * (1.0f / 24.0f));
            s2[q] = b * (1.0f + b2 * (-1.0f / 6.0f + b2 * (1.0f / 120.0f)));
        }
        C.P01[0] = c2[0] * c2[1]; C.P01[1] = s2[0] * c2[1];
        C.P01[2] = c2[0] * s2[1]; C.P01[3] = s2[0] * s2[1];
        C.P23[0] = c2[2] * c2[3]; C.P23[1] = s2[2] * c2[3];
        C.P23[2] = c2[2] * s2[3]; C.P23[3] = s2[2] * s2[3];
        C.c2q1 = c2[1]; C.s2q1 = s2[1];
        C.c2q2 = c2[2]; C.s2q2 = s2[2];
    }

    const int idx = blockIdx.x * 256 + threadIdx.x;
    // out offset o = 16*idx; x offset = o - 8*(idx & 31)  (row-pair layout)
    const int o    = idx << 4;
    const int xoff = o - 8 * (idx & 31);

    const float4 t0 = *reinterpret_cast<const float4*>(x + xoff);        // top, A
    const float4 t1 = *reinterpret_cast<const float4*>(x + xoff + 4);    // top, B
    const float4 b0 = *reinterpret_cast<const float4*>(x + xoff + 256);  // bot, A
    const float4 b1 = *reinterpret_cast<const float4*>(x + xoff + 260);  // bot, B

    const Bloch BA = make_bloch(t0, b0, C);
    const Bloch BB = make_bloch(t1, b1, C);

    const u64x a0 = tsum<TTC.off[0], TTC.off[1]>(BA, C);
    const u64x b0s = tsum<TTC.off[0], TTC.off[1]>(BB, C);
    const u64x a1 = tsum<TTC.off[1], TTC.off[2]>(BA, C);
    const u64x b1s = tsum<TTC.off[1], TTC.off[2]>(BB, C);
    const u64x a2 = tsum<TTC.off[2], TTC.off[3]>(BA, C);
    const u64x b2s = tsum<TTC.off[2], TTC.off[3]>(BB, C);
    const u64x a3 = tsum<TTC.off[3], TTC.off[4]>(BA, C);
    const u64x b3s = tsum<TTC.off[3], TTC.off[4]>(BB, C);

    float a0l, a0h, a1l, a1h, a2l, a2h, a3l, a3h;
    float c0l, c0h, c1l, c1h, c2l, c2h, c3l, c3h;
    unpack2(a0, a0l, a0h); unpack2(a1, a1l, a1h);
    unpack2(a2, a2l, a2h); unpack2(a3, a3l, a3h);
    unpack2(b0s, c0l, c0h); unpack2(b1s, c1l, c1h);
    unpack2(b2s, c2l, c2h); unpack2(b3s, c3l, c3h);

    float4* op = reinterpret_cast<float4*>(out + o);
    op[0] = make_float4(a0l, a1l, a2l, a3l);
    op[1] = make_float4(a0h, a1h, a2h, a3h);
    op[2] = make_float4(c0l, c1l, c2l, c3l);
    op[3] = make_float4(c0h, c1h, c2h, c3h);
}

// ---------------- launch ----------------------------------------------------
extern "C" void kernel_launch(void* const* d_in, const int* in_sizes, int n_in,
                              void* d_out, int out_size) {
    const float* x = (const float*)d_in[0];
    const float* w = (const float*)d_in[1];
    if (n_in >= 2 && in_sizes[0] == 8) {  // defensive: metadata order swap
        const float* t = x; x = w; w = t;
    }
    qmain_kernel<<<512, 256>>>(x, w, (float*)d_out);
}

// round 15
// speedup vs baseline: 1.2250x; 1.2250x over previous
#include <cuda_runtime.h>
#include <cstdint>

// ---------------------------------------------------------------------------
// MinimalQuantumLayer via Heisenberg picture, R15 = R13 with MUFU sincos:
//  - sin/cos(x*pi/2) via __sinf/__cosf (MUFU.SIN/COS, own pipe, rt 8/SMSP,
//    lat 16): removes ~36 packed fma ops/thread (the deg-4 Horner chains,
//    the longest serial dependency) from the 34%-busy fma pipe and puts
//    them on the 0%-busy MUFU pipe. abs err ~4e-7, 2500x under threshold.
//  - everything else identical to R13 (best measured 7.296us kernel):
//    1 item/thread, grid 1024x256, subproduct coefficients, w1 folded into
//    Bloch ey/ez, neg2 signs, tree-split sums, launch_bounds(256,4),
//    strength-reduced addressing.
// ---------------------------------------------------------------------------

typedef unsigned long long u64x;

static __device__ __forceinline__ u64x pack2(float lo, float hi) {
    u64x r;
    asm("mov.b64 %0, {%1, %2};" : "=l"(r)
        : "r"(__float_as_uint(lo)), "r"(__float_as_uint(hi)));
    return r;
}
static __device__ __forceinline__ void unpack2(u64x v, float& lo, float& hi) {
    unsigned a, b;
    asm("mov.b64 {%0, %1}, %2;" : "=r"(a), "=r"(b) : "l"(v));
    lo = __uint_as_float(a); hi = __uint_as_float(b);
}
static __device__ __forceinline__ u64x bcast2(float f) { return pack2(f, f); }
static __device__ __forceinline__ u64x fma2(u64x a, u64x b, u64x c) {
    u64x d;
    asm("fma.rn.f32x2 %0, %1, %2, %3;" : "=l"(d) : "l"(a), "l"(b), "l"(c));
    return d;
}
static __device__ __forceinline__ u64x mul2(u64x a, u64x b) {
    u64x d;
    asm("mul.rn.f32x2 %0, %1, %2;" : "=l"(d) : "l"(a), "l"(b));
    return d;
}
static __device__ __forceinline__ u64x add2(u64x a, u64x b) {
    u64x d;
    asm("add.rn.f32x2 %0, %1, %2;" : "=l"(d) : "l"(a), "l"(b));
    return d;
}
static __device__ __forceinline__ u64x neg2(u64x a) { return a ^ 0x8000000080000000ULL; }

// ---------------- compile-time Pauli-string machinery ----------------------
struct PS { int x, z, ph; };

static __host__ __device__ constexpr PS conj_cnot(PS p, int c, int t) {
    const int xc = (p.x >> c) & 1, zc = (p.z >> c) & 1;
    const int xt = (p.x >> t) & 1, zt = (p.z >> t) & 1;
    const int flip = xc & zt & (xt ^ zc ^ 1);
    return PS{ p.x ^ (xc << t), p.z ^ (zt << c), (p.ph + 2 * flip) & 3 };
}
static __host__ __device__ constexpr PS conj_ring(PS p) {
    p = conj_cnot(p, 3, 0);
    p = conj_cnot(p, 2, 3);
    p = conj_cnot(p, 1, 2);
    p = conj_cnot(p, 0, 1);
    return p;
}
static __host__ __device__ constexpr PS mul_ps(PS a, PS b) {
    int ph = a.ph + b.ph;
    for (int q = 0; q < 4; ++q) {
        const int x1 = (a.x >> q) & 1, z1 = (a.z >> q) & 1;
        const int x2 = (b.x >> q) & 1, z2 = (b.z >> q) & 1;
        ph += x1 * z1 + x2 * z2 + 2 * (z1 & x2) - ((x1 ^ x2) & (z1 ^ z2));
    }
    return PS{ a.x ^ b.x, a.z ^ b.z, ((ph % 4) + 4) & 3 };
}

struct TermTab {
    int off[5];
    int tS[36];        // support mask of this term's observable
    int let[36][4];    // 0=I 1=X 2=Z 3=Y
    int sgn[36];
    int smask[36];     // bit j: factor uses sin(w2_j) (else cos)
};

static __host__ __device__ constexpr TermTab build_terms() {
    TermTab T{};
    int n = 0;
    for (int o = 0; o < 4; ++o) {
        T.off[o] = n;
        const PS Pq = conj_ring(PS{0, 1 << o, 0});   // R2' Z_o R2: pure Z-string
        const int S = Pq.z;
        for (int m = 0; m < 16; ++m) {
            if (m & ~S) continue;
            PS prod{0, 0, 0};
            for (int j = 0; j < 4; ++j) {
                if (!((S >> j) & 1)) continue;
                const PS base = ((m >> j) & 1) ? PS{1 << j, 1 << j, 0}   // Y_j
                                               : PS{0, 1 << j, 0};      // Z_j
                prod = mul_ps(prod, conj_ring(base));                   // R1-conj
            }
            T.tS[n] = S;
            for (int q = 0; q < 4; ++q) {
                const int xb = (prod.x >> q) & 1, zb = (prod.z >> q) & 1;
                T.let[n][q] = xb + 2 * zb;
            }
            T.sgn[n]   = (prod.ph == 0) ? 1 : ((prod.ph == 2) ? -1 : 0);
            T.smask[n] = m;
            ++n;
        }
    }
    T.off[4] = n;
    return T;
}

static constexpr TermTab TTC = build_terms();   // compile-time only
static_assert(TTC.off[4] == 36, "term count");

// ---------------- runtime structures (constant-index access only) -----------
struct Bloch { u64x ex[4], ey[4], ez[4]; };     // <X>, <Y>, <Z> per qubit
struct Ctx {                                    // shared w2 subproducts
    float P01[4], P23[4];                       // qubit{0,1} / {2,3} products
    float c2q1, s2q1, c2q2, s2q2;               // single-qubit leftovers
};

// coefficient of term TI: product of sin/cos(w2_j) over support (sign handled
// separately via neg2 on the packed product). Index bit j of smask selects sin.
template <int TI>
static __device__ __forceinline__ float coefv(const Ctx& C) {
    constexpr int S = TTC.tS[TI], m = TTC.smask[TI];
    constexpr bool lo2 = (S & 3) == 3;               // qubits 0 and 1
    constexpr bool lo1 = !lo2 && ((S & 2) != 0);     // qubit 1 only (o=0)
    constexpr bool hi2 = (S & 12) == 12;             // qubits 2 and 3
    constexpr bool hi1 = !hi2 && ((S & 4) != 0);     // qubit 2 only (o=2)
    if constexpr (lo2 && hi2) return C.P01[m & 3] * C.P23[(m >> 2) & 3];
    else if constexpr (lo2 && hi1)
        return C.P01[m & 3] * (((m >> 2) & 1) ? C.s2q2 : C.c2q2);
    else if constexpr (lo2) return C.P01[m & 3];
    else if constexpr (lo1 && hi2)
        return (((m >> 1) & 1) ? C.s2q1 : C.c2q1) * C.P23[(m >> 2) & 3];
    else if constexpr (hi2) return C.P23[(m >> 2) & 3];
    else return 1.0f;   // unreachable for this circuit
}

// Bloch-product of one term: X -> ex, Z -> ez, Y -> ey, I -> skip
template <int L, int Q>
static __device__ __forceinline__ u64x pick(const Bloch& B) {
    if constexpr (L == 1) return B.ex[Q];
    else if constexpr (L == 2) return B.ez[Q];
    else return B.ey[Q];
}
template <int TI>
static __device__ __forceinline__ u64x pprod(const Bloch& B) {
    constexpr int L0 = TTC.let[TI][0], L1 = TTC.let[TI][1],
                  L2 = TTC.let[TI][2], L3 = TTC.let[TI][3];
    constexpr int f = L0 ? 0 : (L1 ? 1 : (L2 ? 2 : 3));
    u64x m;
    if constexpr (f == 0)      m = pick<L0, 0>(B);
    else if constexpr (f == 1) m = pick<L1, 1>(B);
    else if constexpr (f == 2) m = pick<L2, 2>(B);
    else                       m = pick<L3, 3>(B);
    if constexpr (f < 1 && L1 != 0) m = mul2(m, pick<L1, 1>(B));
    if constexpr (f < 2 && L2 != 0) m = mul2(m, pick<L2, 2>(B));
    if constexpr (f < 3 && L3 != 0) m = mul2(m, pick<L3, 3>(B));
    return m;
}
// packed product with compile-time sign folded (neg2 = alu-pipe XOR)
template <int TI>
static __device__ __forceinline__ u64x sprod(const Bloch& B) {
    const u64x p = pprod<TI>(B);
    if constexpr (TTC.sgn[TI] < 0) return neg2(p);
    else return p;
}

// tree-split sum of terms [TI, TE): short fma chains joined by add2
template <int TI, int TE>
static __device__ __forceinline__ u64x tsum(const Bloch& B, const Ctx& C) {
    if constexpr (TE - TI == 1) {
        return mul2(sprod<TI>(B), bcast2(coefv<TI>(C)));
    } else if constexpr (TE - TI == 2) {
        return fma2(sprod<TI>(B), bcast2(coefv<TI>(C)),
                    mul2(sprod<TI + 1>(B), bcast2(coefv<TI + 1>(C))));
    } else {
        constexpr int MID = TI + (TE - TI) / 2;
        return add2(tsum<TI, MID>(B, C), tsum<MID, TE>(B, C));
    }
}

// ---------------- main kernel ---------------------------------------------
// 262144 threads = 32 (batch) * 128 (rows) * 64 (column pairs);
// lane lo = patch at column 2*c2i, lane hi = column 2*c2i+1.
__global__ void __launch_bounds__(256, 4)
qmain_kernel(const float* __restrict__ x, const float* __restrict__ w8,
             float* __restrict__ out) {
    // warp-uniform weight trig (|w| <= 0.1 -> short Taylor, full angle)
    float c1[4], s1[4];
    Ctx C;
    {
        float c2[4], s2[4];
        const float4 wa = __ldg(reinterpret_cast<const float4*>(w8));
        const float4 wb = __ldg(reinterpret_cast<const float4*>(w8) + 1);
        const float w1[4] = {wa.x, wa.y, wa.z, wa.w};
        const float w2[4] = {wb.x, wb.y, wb.z, wb.w};
#pragma unroll
        for (int q = 0; q < 4; ++q) {
            const float a = w1[q], a2 = a * a;
            c1[q] = 1.0f + a2 * (-0.5f + a2 * (1.0f / 24.0f));
            s1[q] = a * (1.0f + a2 * (-1.0f / 6.0f + a2 * (1.0f / 120.0f)));
            const float b = w2[q], b2 = b * b;
            c2[q] = 1.0f + b2 * (-0.5f + b2 * (1.0f / 24.0f));
            s2[q] = b * (1.0f + b2 * (-1.0f / 6.0f + b2 * (1.0f / 120.0f)));
        }
        C.P01[0] = c2[0] * c2[1]; C.P01[1] = s2[0] * c2[1];
        C.P01[2] = c2[0] * s2[1]; C.P01[3] = s2[0] * s2[1];
        C.P23[0] = c2[2] * c2[3]; C.P23[1] = s2[2] * c2[3];
        C.P23[2] = c2[2] * s2[3]; C.P23[3] = s2[2] * s2[3];
        C.c2q1 = c2[1]; C.s2q1 = s2[1];
        C.c2q2 = c2[2]; C.s2q2 = s2[2];
    }

    const int idx = blockIdx.x * 256 + threadIdx.x;
    // out offset = 8*idx; x offset = 8*idx - 4*(idx & 63)  (row-pair layout)
    const int o8   = idx << 3;
    const int xoff = o8 - 4 * (idx & 63);

    const float4 p0 = *reinterpret_cast<const float4*>(x + xoff);        // row 2r
    const float4 p1 = *reinterpret_cast<const float4*>(x + xoff + 256);  // row 2r+1

    // t = x * pi/2 via MUFU.SIN/COS (own pipe, independent single-shot ops)
    const float PI2 = 1.5707963267948966f;
    const float t0l = p0.x * PI2, t0h = p0.z * PI2;   // qubit 0 (lanes lo, hi)
    const float t1l = p0.y * PI2, t1h = p0.w * PI2;   // qubit 1
    const float t2l = p1.x * PI2, t2h = p1.z * PI2;   // qubit 2
    const float t3l = p1.y * PI2, t3h = p1.w * PI2;   // qubit 3

    u64x st[4], ct[4];
    st[0] = pack2(__sinf(t0l), __sinf(t0h));
    ct[0] = pack2(__cosf(t0l), __cosf(t0h));
    st[1] = pack2(__sinf(t1l), __sinf(t1h));
    ct[1] = pack2(__cosf(t1l), __cosf(t1h));
    st[2] = pack2(__sinf(t2l), __sinf(t2h));
    ct[2] = pack2(__cosf(t2l), __cosf(t2h));
    st[3] = pack2(__sinf(t3l), __sinf(t3h));
    ct[3] = pack2(__cosf(t3l), __cosf(t3h));

    // Bloch: <X>=sin t, <Y>=-s1 cos t, <Z>=c1 cos t
    Bloch B;
#pragma unroll
    for (int q = 0; q < 4; ++q) {
        B.ex[q] = st[q];
        B.ey[q] = mul2(bcast2(-s1[q]), ct[q]);
        B.ez[q] = mul2(bcast2(c1[q]), ct[q]);
    }

    const u64x z0 = tsum<TTC.off[0], TTC.off[1]>(B, C);
    const u64x z1 = tsum<TTC.off[1], TTC.off[2]>(B, C);
    const u64x z2 = tsum<TTC.off[2], TTC.off[3]>(B, C);
    const u64x z3 = tsum<TTC.off[3], TTC.off[4]>(B, C);

    float z0a, z0b, z1a, z1b, z2a, z2b, z3a, z3b;
    unpack2(z0, z0a, z0b);
    unpack2(z1, z1a, z1b);
    unpack2(z2, z2a, z2b);
    unpack2(z3, z3a, z3b);

    reinterpret_cast<float4*>(out + o8)[0] = make_float4(z0a, z1a, z2a, z3a);
    reinterpret_cast<float4*>(out + o8)[1] = make_float4(z0b, z1b, z2b, z3b);
}

// ---------------- launch ----------------------------------------------------
extern "C" void kernel_launch(void* const* d_in, const int* in_sizes, int n_in,
                              void* d_out, int out_size) {
    const float* x = (const float*)d_in[0];
    const float* w = (const float*)d_in[1];
    if (n_in >= 2 && in_sizes[0] == 8) {  // defensive: metadata order swap
        const float* t = x; x = w; w = t;
    }
    qmain_kernel<<<1024, 256>>>(x, w, (float*)d_out);
}

// round 16
// speedup vs baseline: 1.2294x; 1.0036x over previous
#include <cuda_runtime.h>
#include <cstdint>

// ---------------------------------------------------------------------------
// MinimalQuantumLayer via Heisenberg picture, R16 = R15 with the register/
// occupancy push:
//  - Bloch state shrunk to {sin t, cos t} (8 u64x = 16 regs, was 24):
//    w1 letter factors (c1 for Z, -s1 for Y) folded into the warp-uniform
//    per-term scalar coefficients instead of packed ey/ez vectors.
//  - packed neg2 sign ops deleted: circuit sign XOR Y-letter parity folds
//    into the scalar coefficient (free FMUL negation modifier).
//  - __launch_bounds__(256,5): 51-reg target -> 5 CTAs/SM, 40 warps (+25%
//    residency) to fill the 52% idle-issue gap measured in R13/R15.
//  - rest identical to R15: MUFU sincos (own pipe), subproduct w2 coefs,
//    tree-split sums, strength-reduced addressing, 1 item/thread, 1024x256.
// ---------------------------------------------------------------------------

typedef unsigned long long u64x;

static __device__ __forceinline__ u64x pack2(float lo, float hi) {
    u64x r;
    asm("mov.b64 %0, {%1, %2};" : "=l"(r)
        : "r"(__float_as_uint(lo)), "r"(__float_as_uint(hi)));
    return r;
}
static __device__ __forceinline__ void unpack2(u64x v, float& lo, float& hi) {
    unsigned a, b;
    asm("mov.b64 {%0, %1}, %2;" : "=r"(a), "=r"(b) : "l"(v));
    lo = __uint_as_float(a); hi = __uint_as_float(b);
}
static __device__ __forceinline__ u64x bcast2(float f) { return pack2(f, f); }
static __device__ __forceinline__ u64x fma2(u64x a, u64x b, u64x c) {
    u64x d;
    asm("fma.rn.f32x2 %0, %1, %2, %3;" : "=l"(d) : "l"(a), "l"(b), "l"(c));
    return d;
}
static __device__ __forceinline__ u64x mul2(u64x a, u64x b) {
    u64x d;
    asm("mul.rn.f32x2 %0, %1, %2;" : "=l"(d) : "l"(a), "l"(b));
    return d;
}
static __device__ __forceinline__ u64x add2(u64x a, u64x b) {
    u64x d;
    asm("add.rn.f32x2 %0, %1, %2;" : "=l"(d) : "l"(a), "l"(b));
    return d;
}

// ---------------- compile-time Pauli-string machinery ----------------------
struct PS { int x, z, ph; };

static __host__ __device__ constexpr PS conj_cnot(PS p, int c, int t) {
    const int xc = (p.x >> c) & 1, zc = (p.z >> c) & 1;
    const int xt = (p.x >> t) & 1, zt = (p.z >> t) & 1;
    const int flip = xc & zt & (xt ^ zc ^ 1);
    return PS{ p.x ^ (xc << t), p.z ^ (zt << c), (p.ph + 2 * flip) & 3 };
}
static __host__ __device__ constexpr PS conj_ring(PS p) {
    p = conj_cnot(p, 3, 0);
    p = conj_cnot(p, 2, 3);
    p = conj_cnot(p, 1, 2);
    p = conj_cnot(p, 0, 1);
    return p;
}
static __host__ __device__ constexpr PS mul_ps(PS a, PS b) {
    int ph = a.ph + b.ph;
    for (int q = 0; q < 4; ++q) {
        const int x1 = (a.x >> q) & 1, z1 = (a.z >> q) & 1;
        const int x2 = (b.x >> q) & 1, z2 = (b.z >> q) & 1;
        ph += x1 * z1 + x2 * z2 + 2 * (z1 & x2) - ((x1 ^ x2) & (z1 ^ z2));
    }
    return PS{ a.x ^ b.x, a.z ^ b.z, ((ph % 4) + 4) & 3 };
}

struct TermTab {
    int off[5];
    int tS[36];        // support mask of this term's observable
    int let[36][4];    // 0=I 1=X 2=Z 3=Y
    int sgn[36];
    int smask[36];     // bit j: factor uses sin(w2_j) (else cos)
};

static __host__ __device__ constexpr TermTab build_terms() {
    TermTab T{};
    int n = 0;
    for (int o = 0; o < 4; ++o) {
        T.off[o] = n;
        const PS Pq = conj_ring(PS{0, 1 << o, 0});   // R2' Z_o R2: pure Z-string
        const int S = Pq.z;
        for (int m = 0; m < 16; ++m) {
            if (m & ~S) continue;
            PS prod{0, 0, 0};
            for (int j = 0; j < 4; ++j) {
                if (!((S >> j) & 1)) continue;
                const PS base = ((m >> j) & 1) ? PS{1 << j, 1 << j, 0}   // Y_j
                                               : PS{0, 1 << j, 0};      // Z_j
                prod = mul_ps(prod, conj_ring(base));                   // R1-conj
            }
            T.tS[n] = S;
            for (int q = 0; q < 4; ++q) {
                const int xb = (prod.x >> q) & 1, zb = (prod.z >> q) & 1;
                T.let[n][q] = xb + 2 * zb;
            }
            T.sgn[n]   = (prod.ph == 0) ? 1 : ((prod.ph == 2) ? -1 : 0);
            T.smask[n] = m;
            ++n;
        }
    }
    T.off[4] = n;
    return T;
}

static constexpr TermTab TTC = build_terms();   // compile-time only
static_assert(TTC.off[4] == 36, "term count");

// ---------------- runtime structures (constant-index access only) -----------
struct Bloch { u64x ex[4], ct[4]; };            // sin t, cos t per qubit
struct Ctx {                                    // warp-uniform weight context
    float P01[4], P23[4];                       // w2 products qubits {0,1}/{2,3}
    float c2q1, s2q1, c2q2, s2q2;               // single-qubit leftovers
    float c1[4], s1[4];                         // layer-1 weight trig
};

// coefficient of term TI: sign * w2 sin/cos product over support *
// per-letter w1 factor (Z -> c1[q], Y -> s1[q]; Y sign in parity fold).
template <int TI>
static __device__ __forceinline__ float coefv(const Ctx& C) {
    constexpr int S = TTC.tS[TI], m = TTC.smask[TI];
    constexpr int L0 = TTC.let[TI][0], L1 = TTC.let[TI][1],
                  L2 = TTC.let[TI][2], L3 = TTC.let[TI][3];
    constexpr bool lo2 = (S & 3) == 3;               // qubits 0 and 1
    constexpr bool lo1 = !lo2 && ((S & 2) != 0);     // qubit 1 only
    constexpr bool hi2 = (S & 12) == 12;             // qubits 2 and 3
    constexpr bool hi1 = !hi2 && ((S & 4) != 0);     // qubit 2 only
    float c;
    if constexpr (lo2 && hi2) c = C.P01[m & 3] * C.P23[(m >> 2) & 3];
    else if constexpr (lo2 && hi1)
        c = C.P01[m & 3] * (((m >> 2) & 1) ? C.s2q2 : C.c2q2);
    else if constexpr (lo2) c = C.P01[m & 3];
    else if constexpr (lo1 && hi2)
        c = (((m >> 1) & 1) ? C.s2q1 : C.c2q1) * C.P23[(m >> 2) & 3];
    else if constexpr (hi2) c = C.P23[(m >> 2) & 3];
    else c = 1.0f;
    if constexpr (L0 == 2) c *= C.c1[0];
    if constexpr (L0 == 3) c *= C.s1[0];
    if constexpr (L1 == 2) c *= C.c1[1];
    if constexpr (L1 == 3) c *= C.s1[1];
    if constexpr (L2 == 2) c *= C.c1[2];
    if constexpr (L2 == 3) c *= C.s1[2];
    if constexpr (L3 == 2) c *= C.c1[3];
    if constexpr (L3 == 3) c *= C.s1[3];
    constexpr int nY = (L0 == 3) + (L1 == 3) + (L2 == 3) + (L3 == 3);
    constexpr bool neg = (((TTC.sgn[TI] < 0) ? 1 : 0) ^ (nY & 1)) != 0;
    if constexpr (neg) return -c;
    else return c;
}

// Bloch-product of one term: X -> ex[q], Y/Z -> ct[q], I -> skip
template <int L, int Q>
static __device__ __forceinline__ u64x pick(const Bloch& B) {
    if constexpr (L == 1) return B.ex[Q];
    else return B.ct[Q];
}
template <int TI>
static __device__ __forceinline__ u64x pprod(const Bloch& B) {
    constexpr int L0 = TTC.let[TI][0], L1 = TTC.let[TI][1],
                  L2 = TTC.let[TI][2], L3 = TTC.let[TI][3];
    constexpr int f = L0 ? 0 : (L1 ? 1 : (L2 ? 2 : 3));
    u64x m;
    if constexpr (f == 0)      m = pick<L0, 0>(B);
    else if constexpr (f == 1) m = pick<L1, 1>(B);
    else if constexpr (f == 2) m = pick<L2, 2>(B);
    else                       m = pick<L3, 3>(B);
    if constexpr (f < 1 && L1 != 0) m = mul2(m, pick<L1, 1>(B));
    if constexpr (f < 2 && L2 != 0) m = mul2(m, pick<L2, 2>(B));
    if constexpr (f < 3 && L3 != 0) m = mul2(m, pick<L3, 3>(B));
    return m;
}

// tree-split sum of terms [TI, TE): short fma chains joined by add2
template <int TI, int TE>
static __device__ __forceinline__ u64x tsum(const Bloch& B, const Ctx& C) {
    if constexpr (TE - TI == 1) {
        return mul2(pprod<TI>(B), bcast2(coefv<TI>(C)));
    } else if constexpr (TE - TI == 2) {
        return fma2(pprod<TI>(B), bcast2(coefv<TI>(C)),
                    mul2(pprod<TI + 1>(B), bcast2(coefv<TI + 1>(C))));
    } else {
        constexpr int MID = TI + (TE - TI) / 2;
        return add2(tsum<TI, MID>(B, C), tsum<MID, TE>(B, C));
    }
}

// ---------------- main kernel ---------------------------------------------
// 262144 threads = 32 (batch) * 128 (rows) * 64 (column pairs);
// lane lo = patch at column 2*c2i, lane hi = column 2*c2i+1.
__global__ void __launch_bounds__(256, 5)
qmain_kernel(const float* __restrict__ x, const float* __restrict__ w8,
             float* __restrict__ out) {
    // warp-uniform weight trig (|w| <= 0.1 -> short Taylor, full angle)
    Ctx C;
    {
        float c2[4], s2[4];
        const float4 wa = __ldg(reinterpret_cast<const float4*>(w8));
        const float4 wb = __ldg(reinterpret_cast<const float4*>(w8) + 1);
        const float w1[4] = {wa.x, wa.y, wa.z, wa.w};
        const float w2[4] = {wb.x, wb.y, wb.z, wb.w};
#pragma unroll
        for (int q = 0; q < 4; ++q) {
            const float a = w1[q], a2 = a * a;
            C.c1[q] = 1.0f + a2 * (-0.5f + a2 * (1.0f / 24.0f));
            C.s1[q] = a * (1.0f + a2 * (-1.0f / 6.0f + a2 * (1.0f / 120.0f)));
            const float b = w2[q], b2 = b * b;
            c2[q] = 1.0f + b2 * (-0.5f + b2 * (1.0f / 24.0f));
            s2[q] = b * (1.0f + b2 * (-1.0f / 6.0f + b2 * (1.0f / 120.0f)));
        }
        C.P01[0] = c2[0] * c2[1]; C.P01[1] = s2[0] * c2[1];
        C.P01[2] = c2[0] * s2[1]; C.P01[3] = s2[0] * s2[1];
        C.P23[0] = c2[2] * c2[3]; C.P23[1] = s2[2] * c2[3];
        C.P23[2] = c2[2] * s2[3]; C.P23[3] = s2[2] * s2[3];
        C.c2q1 = c2[1]; C.s2q1 = s2[1];
        C.c2q2 = c2[2]; C.s2q2 = s2[2];
    }

    const int idx = blockIdx.x * 256 + threadIdx.x;
    // out offset = 8*idx; x offset = 8*idx - 4*(idx & 63)  (row-pair layout)
    const int o8   = idx << 3;
    const int xoff = o8 - 4 * (idx & 63);

    const float4 p0 = *reinterpret_cast<const float4*>(x + xoff);        // row 2r
    const float4 p1 = *reinterpret_cast<const float4*>(x + xoff + 256);  // row 2r+1

    // t = x * pi/2 via MUFU.SIN/COS (own pipe, independent single-shot ops)
    const float PI2 = 1.5707963267948966f;
    const float t0l = p0.x * PI2, t0h = p0.z * PI2;   // qubit 0 (lanes lo, hi)
    const float t1l = p0.y * PI2, t1h = p0.w * PI2;   // qubit 1
    const float t2l = p1.x * PI2, t2h = p1.z * PI2;   // qubit 2
    const float t3l = p1.y * PI2, t3h = p1.w * PI2;   // qubit 3

    Bloch B;
    B.ex[0] = pack2(__sinf(t0l), __sinf(t0h));
    B.ct[0] = pack2(__cosf(t0l), __cosf(t0h));
    B.ex[1] = pack2(__sinf(t1l), __sinf(t1h));
    B.ct[1] = pack2(__cosf(t1l), __cosf(t1h));
    B.ex[2] = pack2(__sinf(t2l), __sinf(t2h));
    B.ct[2] = pack2(__cosf(t2l), __cosf(t2h));
    B.ex[3] = pack2(__sinf(t3l), __sinf(t3h));
    B.ct[3] = pack2(__cosf(t3l), __cosf(t3h));

    const u64x z0 = tsum<TTC.off[0], TTC.off[1]>(B, C);
    const u64x z1 = tsum<TTC.off[1], TTC.off[2]>(B, C);
    const u64x z2 = tsum<TTC.off[2], TTC.off[3]>(B, C);
    const u64x z3 = tsum<TTC.off[3], TTC.off[4]>(B, C);

    float z0a, z0b, z1a, z1b, z2a, z2b, z3a, z3b;
    unpack2(z0, z0a, z0b);
    unpack2(z1, z1a, z1b);
    unpack2(z2, z2a, z2b);
    unpack2(z3, z3a, z3b);

    reinterpret_cast<float4*>(out + o8)[0] = make_float4(z0a, z1a, z2a, z3a);
    reinterpret_cast<float4*>(out + o8)[1] = make_float4(z0b, z1b, z2b, z3b);
}

// ---------------- launch ----------------------------------------------------
extern "C" void kernel_launch(void* const* d_in, const int* in_sizes, int n_in,
                              void* d_out, int out_size) {
    const float* x = (const float*)d_in[0];
    const float* w = (const float*)d_in[1];
    if (n_in >= 2 && in_sizes[0] == 8) {  // defensive: metadata order swap
        const float* t = x; x = w; w = t;
    }
    qmain_kernel<<<1024, 256>>>(x, w, (float*)d_out);
}

// round 17
// speedup vs baseline: 1.2610x; 1.0257x over previous
#include <cuda_runtime.h>
#include <cstdint>

// ---------------------------------------------------------------------------
// MinimalQuantumLayer via Heisenberg picture, R17:
//  - KEY CHANGE vs R16: the 36 warp-uniform pre-broadcast (u64x) term
//    coefficients are computed ONCE per CTA by thread 0 into shared memory
//    (288 B); every thread then reads them with broadcast LDS.64. This
//    replaces ~130 redundant uniform ALU/MOV instructions per thread with
//    36 LDS — the measured bottleneck is total issued instructions
//    (dur invariant to fma ops / MUFU / occupancy across R13-R16).
//  - x-loads + MUFU sincos issued BEFORE the barrier (overlap thread 0's
//    serial coefficient work).
//  - rest as R16: MUFU sincos, sin/cos-only Bloch (w1+sign folded into
//    coefs), tree-split sums, strength-reduced addressing, 1 item/thread.
// ---------------------------------------------------------------------------

typedef unsigned long long u64x;

static __device__ __forceinline__ u64x pack2(float lo, float hi) {
    u64x r;
    asm("mov.b64 %0, {%1, %2};" : "=l"(r)
        : "r"(__float_as_uint(lo)), "r"(__float_as_uint(hi)));
    return r;
}
static __device__ __forceinline__ void unpack2(u64x v, float& lo, float& hi) {
    unsigned a, b;
    asm("mov.b64 {%0, %1}, %2;" : "=r"(a), "=r"(b) : "l"(v));
    lo = __uint_as_float(a); hi = __uint_as_float(b);
}
static __device__ __forceinline__ u64x bcast2(float f) { return pack2(f, f); }
static __device__ __forceinline__ u64x fma2(u64x a, u64x b, u64x c) {
    u64x d;
    asm("fma.rn.f32x2 %0, %1, %2, %3;" : "=l"(d) : "l"(a), "l"(b), "l"(c));
    return d;
}
static __device__ __forceinline__ u64x mul2(u64x a, u64x b) {
    u64x d;
    asm("mul.rn.f32x2 %0, %1, %2;" : "=l"(d) : "l"(a), "l"(b));
    return d;
}
static __device__ __forceinline__ u64x add2(u64x a, u64x b) {
    u64x d;
    asm("add.rn.f32x2 %0, %1, %2;" : "=l"(d) : "l"(a), "l"(b));
    return d;
}

// ---------------- compile-time Pauli-string machinery ----------------------
struct PS { int x, z, ph; };

static __host__ __device__ constexpr PS conj_cnot(PS p, int c, int t) {
    const int xc = (p.x >> c) & 1, zc = (p.z >> c) & 1;
    const int xt = (p.x >> t) & 1, zt = (p.z >> t) & 1;
    const int flip = xc & zt & (xt ^ zc ^ 1);
    return PS{ p.x ^ (xc << t), p.z ^ (zt << c), (p.ph + 2 * flip) & 3 };
}
static __host__ __device__ constexpr PS conj_ring(PS p) {
    p = conj_cnot(p, 3, 0);
    p = conj_cnot(p, 2, 3);
    p = conj_cnot(p, 1, 2);
    p = conj_cnot(p, 0, 1);
    return p;
}
static __host__ __device__ constexpr PS mul_ps(PS a, PS b) {
    int ph = a.ph + b.ph;
    for (int q = 0; q < 4; ++q) {
        const int x1 = (a.x >> q) & 1, z1 = (a.z >> q) & 1;
        const int x2 = (b.x >> q) & 1, z2 = (b.z >> q) & 1;
        ph += x1 * z1 + x2 * z2 + 2 * (z1 & x2) - ((x1 ^ x2) & (z1 ^ z2));
    }
    return PS{ a.x ^ b.x, a.z ^ b.z, ((ph % 4) + 4) & 3 };
}

struct TermTab {
    int off[5];
    int tS[36];        // support mask of this term's observable
    int let[36][4];    // 0=I 1=X 2=Z 3=Y
    int sgn[36];
    int smask[36];     // bit j: factor uses sin(w2_j) (else cos)
};

static __host__ __device__ constexpr TermTab build_terms() {
    TermTab T{};
    int n = 0;
    for (int o = 0; o < 4; ++o) {
        T.off[o] = n;
        const PS Pq = conj_ring(PS{0, 1 << o, 0});   // R2' Z_o R2: pure Z-string
        const int S = Pq.z;
        for (int m = 0; m < 16; ++m) {
            if (m & ~S) continue;
            PS prod{0, 0, 0};
            for (int j = 0; j < 4; ++j) {
                if (!((S >> j) & 1)) continue;
                const PS base = ((m >> j) & 1) ? PS{1 << j, 1 << j, 0}   // Y_j
                                               : PS{0, 1 << j, 0};      // Z_j
                prod = mul_ps(prod, conj_ring(base));                   // R1-conj
            }
            T.tS[n] = S;
            for (int q = 0; q < 4; ++q) {
                const int xb = (prod.x >> q) & 1, zb = (prod.z >> q) & 1;
                T.let[n][q] = xb + 2 * zb;
            }
            T.sgn[n]   = (prod.ph == 0) ? 1 : ((prod.ph == 2) ? -1 : 0);
            T.smask[n] = m;
            ++n;
        }
    }
    T.off[4] = n;
    return T;
}

static constexpr TermTab TTC = build_terms();   // compile-time only
static_assert(TTC.off[4] == 36, "term count");

// ---------------- runtime structures (constant-index access only) -----------
struct Bloch { u64x ex[4], ct[4]; };            // sin t, cos t per qubit
struct Ctx {                                    // warp-uniform weight context
    float P01[4], P23[4];                       // w2 products qubits {0,1}/{2,3}
    float c2q1, s2q1, c2q2, s2q2;               // single-qubit leftovers
    float c1[4], s1[4];                         // layer-1 weight trig
};

// coefficient of term TI: sign * w2 sin/cos product over support *
// per-letter w1 factor (Z -> c1[q], Y -> s1[q]; Y's -i sign in parity fold).
template <int TI>
static __device__ __forceinline__ float coefv(const Ctx& C) {
    constexpr int S = TTC.tS[TI], m = TTC.smask[TI];
    constexpr int L0 = TTC.let[TI][0], L1 = TTC.let[TI][1],
                  L2 = TTC.let[TI][2], L3 = TTC.let[TI][3];
    constexpr bool lo2 = (S & 3) == 3;               // qubits 0 and 1
    constexpr bool lo1 = !lo2 && ((S & 2) != 0);     // qubit 1 only
    constexpr bool hi2 = (S & 12) == 12;             // qubits 2 and 3
    constexpr bool hi1 = !hi2 && ((S & 4) != 0);     // qubit 2 only
    float c;
    if constexpr (lo2 && hi2) c = C.P01[m & 3] * C.P23[(m >> 2) & 3];
    else if constexpr (lo2 && hi1)
        c = C.P01[m & 3] * (((m >> 2) & 1) ? C.s2q2 : C.c2q2);
    else if constexpr (lo2) c = C.P01[m & 3];
    else if constexpr (lo1 && hi2)
        c = (((m >> 1) & 1) ? C.s2q1 : C.c2q1) * C.P23[(m >> 2) & 3];
    else if constexpr (hi2) c = C.P23[(m >> 2) & 3];
    else c = 1.0f;
    if constexpr (L0 == 2) c *= C.c1[0];
    if constexpr (L0 == 3) c *= C.s1[0];
    if constexpr (L1 == 2) c *= C.c1[1];
    if constexpr (L1 == 3) c *= C.s1[1];
    if constexpr (L2 == 2) c *= C.c1[2];
    if constexpr (L2 == 3) c *= C.s1[2];
    if constexpr (L3 == 2) c *= C.c1[3];
    if constexpr (L3 == 3) c *= C.s1[3];
    constexpr int nY = (L0 == 3) + (L1 == 3) + (L2 == 3) + (L3 == 3);
    constexpr bool neg = (((TTC.sgn[TI] < 0) ? 1 : 0) ^ (nY & 1)) != 0;
    if constexpr (neg) return -c;
    else return c;
}

// store all 36 pre-broadcast coefficients to smem (thread 0 only)
template <int TI, int TE>
static __device__ __forceinline__ void store_coefs(u64x* sC, const Ctx& C) {
    sC[TI] = bcast2(coefv<TI>(C));
    if constexpr (TI + 1 < TE) store_coefs<TI + 1, TE>(sC, C);
}

// Bloch-product of one term: X -> ex[q], Y/Z -> ct[q], I -> skip
template <int L, int Q>
static __device__ __forceinline__ u64x pick(const Bloch& B) {
    if constexpr (L == 1) return B.ex[Q];
    else return B.ct[Q];
}
template <int TI>
static __device__ __forceinline__ u64x pprod(const Bloch& B) {
    constexpr int L0 = TTC.let[TI][0], L1 = TTC.let[TI][1],
                  L2 = TTC.let[TI][2], L3 = TTC.let[TI][3];
    constexpr int f = L0 ? 0 : (L1 ? 1 : (L2 ? 2 : 3));
    u64x m;
    if constexpr (f == 0)      m = pick<L0, 0>(B);
    else if constexpr (f == 1) m = pick<L1, 1>(B);
    else if constexpr (f == 2) m = pick<L2, 2>(B);
    else                       m = pick<L3, 3>(B);
    if constexpr (f < 1 && L1 != 0) m = mul2(m, pick<L1, 1>(B));
    if constexpr (f < 2 && L2 != 0) m = mul2(m, pick<L2, 2>(B));
    if constexpr (f < 3 && L3 != 0) m = mul2(m, pick<L3, 3>(B));
    return m;
}

// tree-split sum of terms [TI, TE): coefs read from smem (broadcast LDS.64)
template <int TI, int TE>
static __device__ __forceinline__ u64x tsum(const Bloch& B, const u64x* sC) {
    if constexpr (TE - TI == 1) {
        return mul2(pprod<TI>(B), sC[TI]);
    } else if constexpr (TE - TI == 2) {
        return fma2(pprod<TI>(B), sC[TI],
                    mul2(pprod<TI + 1>(B), sC[TI + 1]));
    } else {
        constexpr int MID = TI + (TE - TI) / 2;
        return add2(tsum<TI, MID>(B, sC), tsum<MID, TE>(B, sC));
    }
}

// ---------------- main kernel ---------------------------------------------
// 262144 threads = 32 (batch) * 128 (rows) * 64 (column pairs);
// lane lo = patch at column 2*c2i, lane hi = column 2*c2i+1.
__global__ void __launch_bounds__(256, 4)
qmain_kernel(const float* __restrict__ x, const float* __restrict__ w8,
             float* __restrict__ out) {
    __shared__ u64x sC[36];

    const int idx = blockIdx.x * 256 + threadIdx.x;
    // out offset = 8*idx; x offset = 8*idx - 4*(idx & 63)  (row-pair layout)
    const int o8   = idx << 3;
    const int xoff = o8 - 4 * (idx & 63);

    // issue data loads FIRST (overlap thread 0's coefficient work)
    const float4 p0 = *reinterpret_cast<const float4*>(x + xoff);        // row 2r
    const float4 p1 = *reinterpret_cast<const float4*>(x + xoff + 256);  // row 2r+1

    // thread 0: weight trig + 36 pre-broadcast coefficients into smem
    if (threadIdx.x == 0) {
        Ctx C;
        float c2[4], s2[4];
        const float4 wa = __ldg(reinterpret_cast<const float4*>(w8));
        const float4 wb = __ldg(reinterpret_cast<const float4*>(w8) + 1);
        const float w1[4] = {wa.x, wa.y, wa.z, wa.w};
        const float w2[4] = {wb.x, wb.y, wb.z, wb.w};
#pragma unroll
        for (int q = 0; q < 4; ++q) {
            const float a = w1[q], a2 = a * a;
            C.c1[q] = 1.0f + a2 * (-0.5f + a2 * (1.0f / 24.0f));
            C.s1[q] = a * (1.0f + a2 * (-1.0f / 6.0f + a2 * (1.0f / 120.0f)));
            const float b = w2[q], b2 = b * b;
            c2[q] = 1.0f + b2 * (-0.5f + b2 * (1.0f / 24.0f));
            s2[q] = b * (1.0f + b2 * (-1.0f / 6.0f + b2 * (1.0f / 120.0f)));
        }
        C.P01[0] = c2[0] * c2[1]; C.P01[1] = s2[0] * c2[1];
        C.P01[2] = c2[0] * s2[1]; C.P01[3] = s2[0] * s2[1];
        C.P23[0] = c2[2] * c2[3]; C.P23[1] = s2[2] * c2[3];
        C.P23[2] = c2[2] * s2[3]; C.P23[3] = s2[2] * s2[3];
        C.c2q1 = c2[1]; C.s2q1 = s2[1];
        C.c2q2 = c2[2]; C.s2q2 = s2[2];
        store_coefs<0, 36>(sC, C);
    }

    // t = x * pi/2 via MUFU.SIN/COS (own pipe; also overlaps thread 0)
    const float PI2 = 1.5707963267948966f;
    const float t0l = p0.x * PI2, t0h = p0.z * PI2;   // qubit 0 (lanes lo, hi)
    const float t1l = p0.y * PI2, t1h = p0.w * PI2;   // qubit 1
    const float t2l = p1.x * PI2, t2h = p1.z * PI2;   // qubit 2
    const float t3l = p1.y * PI2, t3h = p1.w * PI2;   // qubit 3

    Bloch B;
    B.ex[0] = pack2(__sinf(t0l), __sinf(t0h));
    B.ct[0] = pack2(__cosf(t0l), __cosf(t0h));
    B.ex[1] = pack2(__sinf(t1l), __sinf(t1h));
    B.ct[1] = pack2(__cosf(t1l), __cosf(t1h));
    B.ex[2] = pack2(__sinf(t2l), __sinf(t2h));
    B.ct[2] = pack2(__cosf(t2l), __cosf(t2h));
    B.ex[3] = pack2(__sinf(t3l), __sinf(t3h));
    B.ct[3] = pack2(__cosf(t3l), __cosf(t3h));

    __syncthreads();

    const u64x z0 = tsum<TTC.off[0], TTC.off[1]>(B, sC);
    const u64x z1 = tsum<TTC.off[1], TTC.off[2]>(B, sC);
    const u64x z2 = tsum<TTC.off[2], TTC.off[3]>(B, sC);
    const u64x z3 = tsum<TTC.off[3], TTC.off[4]>(B, sC);

    float z0a, z0b, z1a, z1b, z2a, z2b, z3a, z3b;
    unpack2(z0, z0a, z0b);
    unpack2(z1, z1a, z1b);
    unpack2(z2, z2a, z2b);
    unpack2(z3, z3a, z3b);

    reinterpret_cast<float4*>(out + o8)[0] = make_float4(z0a, z1a, z2a, z3a);
    reinterpret_cast<float4*>(out + o8)[1] = make_float4(z0b, z1b, z2b, z3b);
}

// ---------------- launch ----------------------------------------------------
extern "C" void kernel_launch(void* const* d_in, const int* in_sizes, int n_in,
                              void* d_out, int out_size) {
    const float* x = (const float*)d_in[0];
    const float* w = (const float*)d_in[1];
    if (n_in >= 2 && in_sizes[0] == 8) {  // defensive: metadata order swap
        const float* t = x; x = w; w = t;
    }
    qmain_kernel<<<1024, 256>>>(x, w, (float*)d_out);
}